// round 9
// baseline (speedup 1.0000x reference)
#include <cuda_runtime.h>
#include <math.h>

// SPD log-map: one CTA per 64x64 SPD matrix.
// One-sided Jacobi on W = A (stored transposed in smem; row j of Ws = column j of W).
// After convergence: lambda_j = ||w_j||, u_j = w_j/||w_j||.
// Output L[r][c] = sum_j (log(l_j)/l_j^2) * w_j[r] * w_j[c], upper-tri row-major.

#define NMAT   8192
#define NDIM   64
#define PITCH  68      // floats per row: 16B-aligned (68*4=272), staggers banks across rows
#define NTHR   256
#define MAXSWEEP 16

__global__ __launch_bounds__(NTHR, 8)
void spd_logmap_kernel(const float* __restrict__ in, float* __restrict__ out)
{
    __shared__ float Ws[NDIM][PITCH];
    __shared__ float cs[32], sn[32];
    __shared__ int   pr[32], qr[32];
    __shared__ float sj[NDIM];
    __shared__ int   mxbits;   // bit pattern of max relative off-diag^2 this sweep

    const int b   = blockIdx.x;
    const int tid = threadIdx.x;

    // Load A (symmetric, so row j of A == column j of A). Ws[j][i] = A[j][i].
    const float* Ab = in + (size_t)b * (NDIM * NDIM);
    #pragma unroll
    for (int idx = tid; idx < NDIM * NDIM; idx += NTHR)
        Ws[idx >> 6][idx & 63] = Ab[idx];
    if (tid == 0) mxbits = 0;
    __syncthreads();

    const int k = tid >> 3;   // pair index 0..31
    const int l = tid & 7;    // lane within pair-group

    for (int sweep = 0; sweep < MAXSWEEP; ++sweep) {
        for (int r = 0; r < 63; ++r) {
            // ---- pair schedule (round-robin tournament, slot 63 fixed) ----
            if (tid < 32) {
                int p, q;
                if (tid == 0) { p = 63; q = r; }
                else {
                    p = (r + tid) % 63;
                    q = (r - tid + 63) % 63;
                }
                if (p > q) { int t = p; p = q; q = t; }
                pr[tid] = p; qr[tid] = q;
            }
            __syncthreads();

            // ---- Gram dots: bpp, bpq, bqq per pair (8 lanes per pair) ----
            {
                const int p = pr[k], q = qr[k];
                const float4* wp = (const float4*)Ws[p];
                const float4* wq = (const float4*)Ws[q];
                float bpp = 0.f, bpq = 0.f, bqq = 0.f;
                #pragma unroll
                for (int cch = 0; cch < 2; ++cch) {
                    float4 xp = wp[l + 8 * cch];
                    float4 xq = wq[l + 8 * cch];
                    bpp += xp.x * xp.x + xp.y * xp.y + xp.z * xp.z + xp.w * xp.w;
                    bqq += xq.x * xq.x + xq.y * xq.y + xq.z * xq.z + xq.w * xq.w;
                    bpq += xp.x * xq.x + xp.y * xq.y + xp.z * xq.z + xp.w * xq.w;
                }
                #pragma unroll
                for (int off = 4; off > 0; off >>= 1) {
                    bpp += __shfl_down_sync(0xffffffffu, bpp, off);
                    bpq += __shfl_down_sync(0xffffffffu, bpq, off);
                    bqq += __shfl_down_sync(0xffffffffu, bqq, off);
                }
                if (l == 0) {
                    float c = 1.f, s = 0.f;
                    if (fabsf(bpq) > 1e-30f) {
                        float tau = (bqq - bpp) / (2.f * bpq);
                        float t   = copysignf(1.f / (fabsf(tau) + sqrtf(1.f + tau * tau)), tau);
                        c = rsqrtf(1.f + t * t);
                        s = t * c;
                    }
                    cs[k] = c; sn[k] = s;
                    // relative off-diagonal^2 for convergence test (bpp,bqq > 0 for SPD)
                    float rel2 = (bpq * bpq) / (bpp * bqq);
                    atomicMax(&mxbits, __float_as_int(rel2));
                }
            }
            __syncthreads();

            // ---- apply rotation to columns p,q (rows of Ws) ----
            {
                const float c = cs[k], s = sn[k];
                const int p = pr[k], q = qr[k];
                float4* wp = (float4*)Ws[p];
                float4* wq = (float4*)Ws[q];
                #pragma unroll
                for (int cch = 0; cch < 2; ++cch) {
                    const int j = l + 8 * cch;
                    float4 xp = wp[j], xq = wq[j];
                    float4 np, nq;
                    np.x = c * xp.x - s * xq.x;  nq.x = s * xp.x + c * xq.x;
                    np.y = c * xp.y - s * xq.y;  nq.y = s * xp.y + c * xq.y;
                    np.z = c * xp.z - s * xq.z;  nq.z = s * xp.z + c * xq.z;
                    np.w = c * xp.w - s * xq.w;  nq.w = s * xp.w + c * xq.w;
                    wp[j] = np; wq[j] = nq;
                }
            }
            __syncthreads();
        }
        // ---- race-free early exit (relative criterion) ----
        const float m = __int_as_float(mxbits);  // max bpq^2/(bpp*bqq) seen this sweep
        __syncthreads();
        if (m < 4e-10f) break;                   // all pairs had |bpq| < 2e-5*sqrt(bpp*bqq)
        if (tid == 0) mxbits = 0;                // consumed only after next schedule barrier
    }

    // ---- eigen extraction: sj = log(lambda)/lambda^2 = 0.5*log(nrm)/nrm ----
    __syncthreads();
    if (tid < NDIM) {
        const float* w = Ws[tid];
        float nrm = 0.f;
        #pragma unroll
        for (int i = 0; i < NDIM; ++i) nrm += w[i] * w[i];
        sj[tid] = 0.5f * __logf(nrm) / nrm;
    }
    __syncthreads();

    // ---- output: upper triangle row-major: L[r][c] = sum_j sj * w_j[r] * w_j[c] ----
    float* outb = out + (size_t)b * 2080;
    for (int e = tid; e < 2080; e += NTHR) {
        // row r: largest r with r*(129-r)/2 <= e
        int r = (int)((129.0f - sqrtf(16641.0f - 8.0f * (float)e)) * 0.5f);
        if (r < 0) r = 0;
        while (r > 0 && (r * (129 - r)) / 2 > e) --r;
        while (((r + 1) * (129 - (r + 1))) / 2 <= e) ++r;
        const int c = e - (r * (129 - r)) / 2 + r;

        float acc = 0.f;
        #pragma unroll
        for (int j = 0; j < NDIM; ++j)
            acc += (sj[j] * Ws[j][r]) * Ws[j][c];
        outb[e] = acc;
    }
}

extern "C" void kernel_launch(void* const* d_in, const int* in_sizes, int n_in,
                              void* d_out, int out_size)
{
    const float* A = (const float*)d_in[0];
    float* out = (float*)d_out;
    spd_logmap_kernel<<<NMAT, NTHR>>>(A, out);
}

// round 11
// speedup vs baseline: 1.9232x; 1.9232x over previous
#include <cuda_runtime.h>
#include <math.h>

// SPD log-map: one CTA per 64x64 SPD matrix.
// One-sided Jacobi on W = A (row j of smem Ws = column j of W).
// Fused step: load both columns once, butterfly-reduce Gram dots so every lane
// has them, compute c,s redundantly per lane, rotate in registers, store once.
// 1 barrier per step. Schedule kept in per-thread registers (incremental mod 63).
// After convergence: lambda_j = ||w_j||^2 via row norms; output
// L[r][c] = sum_j (0.5*log(nrm_j)/nrm_j) * w_j[r] * w_j[c], upper-tri row-major.

#define NMAT   8192
#define NDIM   64
#define PITCH  68      // floats per row: 16B-aligned, staggers banks across rows
#define NTHR   256
#define MAXSWEEP 16

__global__ __launch_bounds__(NTHR, 8)
void spd_logmap_kernel(const float* __restrict__ in, float* __restrict__ out)
{
    __shared__ float Ws[NDIM][PITCH];
    __shared__ float sj[NDIM];
    __shared__ int   mx[2];    // per-sweep max relative off-diag^2 (float bits), parity-buffered

    const int b   = blockIdx.x;
    const int tid = threadIdx.x;

    // Load A (symmetric => row j of A == column j of A). Ws[j][i] = A[j][i].
    const float* Ab = in + (size_t)b * (NDIM * NDIM);
    #pragma unroll
    for (int idx = tid; idx < NDIM * NDIM; idx += NTHR)
        Ws[idx >> 6][idx & 63] = Ab[idx];
    if (tid == 0) { mx[0] = 0; mx[1] = 0; }
    __syncthreads();

    const int k = tid >> 3;   // pair index 0..31
    const int l = tid & 7;    // lane within pair-group
    const bool lead = (l == 0);

    for (int sweep = 0; sweep < MAXSWEEP; ++sweep) {
        // schedule registers: k==0 -> (63, r); else ((r+k)%63, (r-k+63)%63)
        int p = (k == 0) ? 63 : k;
        int q = (k == 0) ? 0  : 63 - k;

        for (int r = 0; r < 63; ++r) {
            float4* wp = (float4*)Ws[p];
            float4* wq = (float4*)Ws[q];

            // ---- single load of both columns (4x LDS.128 per thread) ----
            float4 xp0 = wp[l],     xp1 = wp[l + 8];
            float4 xq0 = wq[l],     xq1 = wq[l + 8];

            // ---- Gram partial dots ----
            float bpp = xp0.x*xp0.x + xp0.y*xp0.y + xp0.z*xp0.z + xp0.w*xp0.w
                      + xp1.x*xp1.x + xp1.y*xp1.y + xp1.z*xp1.z + xp1.w*xp1.w;
            float bqq = xq0.x*xq0.x + xq0.y*xq0.y + xq0.z*xq0.z + xq0.w*xq0.w
                      + xq1.x*xq1.x + xq1.y*xq1.y + xq1.z*xq1.z + xq1.w*xq1.w;
            float bpq = xp0.x*xq0.x + xp0.y*xq0.y + xp0.z*xq0.z + xp0.w*xq0.w
                      + xp1.x*xq1.x + xp1.y*xq1.y + xp1.z*xq1.z + xp1.w*xq1.w;

            // ---- butterfly reduce within 8-lane group: all lanes get full sums ----
            #pragma unroll
            for (int off = 4; off > 0; off >>= 1) {
                bpp += __shfl_xor_sync(0xffffffffu, bpp, off);
                bqq += __shfl_xor_sync(0xffffffffu, bqq, off);
                bpq += __shfl_xor_sync(0xffffffffu, bpq, off);
            }

            // ---- rotation angle (computed redundantly by all 8 lanes) ----
            float c = 1.f, s = 0.f;
            if (fabsf(bpq) > 1e-30f) {
                float tau = (bqq - bpp) / (2.f * bpq);
                float t   = copysignf(1.f / (fabsf(tau) + sqrtf(1.f + tau * tau)), tau);
                c = rsqrtf(1.f + t * t);
                s = t * c;
            }
            if (lead) {
                float rel2 = (bpq * bpq) / (bpp * bqq);   // bpp,bqq > 0 for SPD
                atomicMax(&mx[sweep & 1], __float_as_int(rel2));
            }

            // ---- rotate in registers, single store (4x STS.128) ----
            float4 np, nq;
            np.x = c*xp0.x - s*xq0.x;  nq.x = s*xp0.x + c*xq0.x;
            np.y = c*xp0.y - s*xq0.y;  nq.y = s*xp0.y + c*xq0.y;
            np.z = c*xp0.z - s*xq0.z;  nq.z = s*xp0.z + c*xq0.z;
            np.w = c*xp0.w - s*xq0.w;  nq.w = s*xp0.w + c*xq0.w;
            wp[l] = np;  wq[l] = nq;
            np.x = c*xp1.x - s*xq1.x;  nq.x = s*xp1.x + c*xq1.x;
            np.y = c*xp1.y - s*xq1.y;  nq.y = s*xp1.y + c*xq1.y;
            np.z = c*xp1.z - s*xq1.z;  nq.z = s*xp1.z + c*xq1.z;
            np.w = c*xp1.w - s*xq1.w;  nq.w = s*xp1.w + c*xq1.w;
            wp[l + 8] = np;  wq[l + 8] = nq;

            // ---- advance schedule (incremental mod 63; k==0 keeps p=63) ----
            if (k != 0) p = (p == 62) ? 0 : p + 1;
            q = (q == 62) ? 0 : q + 1;

            __syncthreads();   // next step's owners read what we just wrote
        }

        // ---- race-free early exit: mx[sweep&1] stable after last step barrier.
        // Next sweep accumulates into mx[(sweep+1)&1], which tid0 pre-zeroes for
        // sweep+2 only after it has been consumed -> init covers first two sweeps,
        // and we re-zero the buffer we just read (it is next used in sweep+2).
        const float m = __int_as_float(mx[sweep & 1]);
        __syncthreads();
        if (m < 4e-10f) break;              // all pairs: |bpq| < 2e-5*sqrt(bpp*bqq)
        if (tid == 0) mx[sweep & 1] = 0;    // safe: written again only in sweep+2,
                                            // separated by >=63 barriers
    }

    // ---- eigen extraction: sj = log(lambda)/lambda^2 = 0.5*log(nrm)/nrm ----
    __syncthreads();
    if (tid < NDIM) {
        const float* w = Ws[tid];
        float nrm = 0.f;
        #pragma unroll
        for (int i = 0; i < NDIM; ++i) nrm += w[i] * w[i];
        sj[tid] = 0.5f * __logf(nrm) / nrm;
    }
    __syncthreads();

    // ---- output: upper triangle row-major: L[r][c] = sum_j sj * w_j[r] * w_j[c] ----
    float* outb = out + (size_t)b * 2080;
    for (int e = tid; e < 2080; e += NTHR) {
        int r = (int)((129.0f - sqrtf(16641.0f - 8.0f * (float)e)) * 0.5f);
        if (r < 0) r = 0;
        while (r > 0 && (r * (129 - r)) / 2 > e) --r;
        while (((r + 1) * (129 - (r + 1))) / 2 <= e) ++r;
        const int c = e - (r * (129 - r)) / 2 + r;

        float acc = 0.f;
        #pragma unroll
        for (int j = 0; j < NDIM; ++j)
            acc += (sj[j] * Ws[j][r]) * Ws[j][c];
        outb[e] = acc;
    }
}

extern "C" void kernel_launch(void* const* d_in, const int* in_sizes, int n_in,
                              void* d_out, int out_size)
{
    const float* A = (const float*)d_in[0];
    float* out = (float*)d_out;
    spd_logmap_kernel<<<NMAT, NTHR>>>(A, out);
}

// round 15
// speedup vs baseline: 2.1110x; 1.0977x over previous
#include <cuda_runtime.h>
#include <math.h>

// SPD log-map: one CTA per 64x64 SPD matrix. One-sided Jacobi.
// Incremental column-norm tracking (bpp/bqq via Jacobi update identity, stored
// in smem nrm[64]) -> only the cross-dot bpq is computed per step (8 FMA + 3
// shfl). Branchless rotation coefficients. Per-thread boolean convergence flag,
// one atomicOr per sweep. Exit sweep's rotations still apply => residual ~tol^2.

#define NMAT   8192
#define NDIM   64
#define PITCH  68      // floats per row: 16B-aligned, staggers banks across rows
#define NTHR   256
#define MAXSWEEP 16
#define TOL    1e-5f   // on bpq^2/(bpp*bqq); post-exit residual ~ TOL^2

__global__ __launch_bounds__(NTHR, 8)
void spd_logmap_kernel(const float* __restrict__ in, float* __restrict__ out)
{
    __shared__ float Ws[NDIM][PITCH];
    __shared__ float nrm[NDIM];   // running squared column norms
    __shared__ float sj[NDIM];
    __shared__ int   fconv;       // OR of "some pair not converged" this sweep

    const int b   = blockIdx.x;
    const int tid = threadIdx.x;

    // Load A (symmetric => row j of A == column j of A). Ws[j][i] = A[j][i].
    const float* Ab = in + (size_t)b * (NDIM * NDIM);
    #pragma unroll
    for (int idx = tid; idx < NDIM * NDIM; idx += NTHR)
        Ws[idx >> 6][idx & 63] = Ab[idx];
    if (tid == 0) fconv = 0;
    __syncthreads();

    // initial squared norms
    if (tid < NDIM) {
        const float* w = Ws[tid];
        float nr = 0.f;
        #pragma unroll
        for (int i = 0; i < NDIM; ++i) nr += w[i] * w[i];
        nrm[tid] = nr;
    }
    __syncthreads();

    const int k = tid >> 3;   // pair index 0..31
    const int l = tid & 7;    // lane within pair-group

    for (int sweep = 0; sweep < MAXSWEEP; ++sweep) {
        // schedule registers: k==0 -> (63, r); else ((r+k)%63, (r-k+63)%63)
        int p = (k == 0) ? 63 : k;
        int q = (k == 0) ? 0  : 63 - k;
        int flag = 0;

        for (int r = 0; r < 63; ++r) {
            float4* wp = (float4*)Ws[p];
            float4* wq = (float4*)Ws[q];
            const float bpp = nrm[p];          // broadcast within group
            const float bqq = nrm[q];

            // ---- single load of both columns (4x LDS.128 per thread) ----
            float4 xp0 = wp[l], xp1 = wp[l + 8];
            float4 xq0 = wq[l], xq1 = wq[l + 8];

            // ---- cross dot only ----
            float bpq = xp0.x*xq0.x + xp0.y*xq0.y + xp0.z*xq0.z + xp0.w*xq0.w
                      + xp1.x*xq1.x + xp1.y*xq1.y + xp1.z*xq1.z + xp1.w*xq1.w;
            #pragma unroll
            for (int off = 4; off > 0; off >>= 1)
                bpq += __shfl_xor_sync(0xffffffffu, bpq, off);

            // ---- convergence flag (branchless, no div) ----
            const float bpq2 = bpq * bpq;
            flag |= (bpq2 >= TOL * (bpp * bqq)) ? 1 : 0;

            // ---- branchless rotation coefficients ----
            // bpq=0, bqq!=bpp: tau=+-inf -> t=0 naturally.
            // bpq=0, bqq==bpp: tau=NaN -> SEL forces t=0.
            float tau = __fdividef(bqq - bpp, 2.f * bpq);
            float t   = copysignf(__fdividef(1.f, fabsf(tau) + sqrtf(1.f + tau * tau)), tau);
            t = (bpq2 >= 1e-38f) ? t : 0.f;
            const float c = rsqrtf(1.f + t * t);
            const float s = t * c;

            // ---- rotate in registers, single store (4x STS.128) ----
            float4 np, nq;
            np.x = c*xp0.x - s*xq0.x;  nq.x = s*xp0.x + c*xq0.x;
            np.y = c*xp0.y - s*xq0.y;  nq.y = s*xp0.y + c*xq0.y;
            np.z = c*xp0.z - s*xq0.z;  nq.z = s*xp0.z + c*xq0.z;
            np.w = c*xp0.w - s*xq0.w;  nq.w = s*xp0.w + c*xq0.w;
            wp[l] = np;  wq[l] = nq;
            np.x = c*xp1.x - s*xq1.x;  nq.x = s*xp1.x + c*xq1.x;
            np.y = c*xp1.y - s*xq1.y;  nq.y = s*xp1.y + c*xq1.y;
            np.z = c*xp1.z - s*xq1.z;  nq.z = s*xp1.z + c*xq1.z;
            np.w = c*xp1.w - s*xq1.w;  nq.w = s*xp1.w + c*xq1.w;
            wp[l + 8] = np;  wq[l + 8] = nq;

            // ---- incremental norm update (Jacobi identity), lane 0 only ----
            if (l == 0) {
                nrm[p] = bpp - t * bpq;
                nrm[q] = bqq + t * bpq;
            }

            // ---- advance schedule (incremental mod 63; k==0 keeps p=63) ----
            if (k != 0) p = (p == 62) ? 0 : p + 1;
            q = (q == 62) ? 0 : q + 1;

            __syncthreads();   // next step's owners read what we just wrote
        }

        // ---- sweep-end convergence decision (race-free) ----
        const int any = __any_sync(0xffffffffu, flag);
        if ((tid & 31) == 0 && any) atomicOr(&fconv, 1);
        __syncthreads();
        const int unconverged = fconv;
        __syncthreads();                    // all reads done before reset
        if (!unconverged) break;            // uniform decision
        if (tid == 0) fconv = 0;            // next atomicOr is >=63 barriers away
    }

    // ---- eigen extraction: recompute exact norms; sj = 0.5*log(nrm)/nrm ----
    __syncthreads();
    if (tid < NDIM) {
        const float* w = Ws[tid];
        float nr = 0.f;
        #pragma unroll
        for (int i = 0; i < NDIM; ++i) nr += w[i] * w[i];
        sj[tid] = 0.5f * __logf(nr) / nr;
    }
    __syncthreads();

    // ---- output: upper triangle row-major: L[r][c] = sum_j sj * w_j[r] * w_j[c] ----
    float* outb = out + (size_t)b * 2080;
    for (int e = tid; e < 2080; e += NTHR) {
        int r = (int)((129.0f - sqrtf(16641.0f - 8.0f * (float)e)) * 0.5f);
        if (r < 0) r = 0;
        while (r > 0 && (r * (129 - r)) / 2 > e) --r;
        while (((r + 1) * (129 - (r + 1))) / 2 <= e) ++r;
        const int c = e - (r * (129 - r)) / 2 + r;

        float acc = 0.f;
        #pragma unroll
        for (int j = 0; j < NDIM; ++j)
            acc += (sj[j] * Ws[j][r]) * Ws[j][c];
        outb[e] = acc;
    }
}

extern "C" void kernel_launch(void* const* d_in, const int* in_sizes, int n_in,
                              void* d_out, int out_size)
{
    const float* A = (const float*)d_in[0];
    float* out = (float*)d_out;
    spd_logmap_kernel<<<NMAT, NTHR>>>(A, out);
}